// round 9
// baseline (speedup 1.0000x reference)
#include <cuda_runtime.h>

#define B 4
#define C 32
#define H 256
#define W 256
#define H3 768
#define W3 768
#define PLANE_IN  65536
#define PLANE_OUT 589824
#define STRIP 8
#define NTHR 384

// out[p, I, J] = x[p, reflect(I/3+I%3-1), reflect(J/3+J%3-1)]
//                * (I==767?2:1) * (J==767?2:1)
// No smem: each output row reads exactly one input row; L1/L2 provide reuse.
__global__ __launch_bounds__(NTHR)
void deform_direct_kernel(const float* __restrict__ x, float* __restrict__ out) {
    const int tid   = threadIdx.x;
    const int base  = blockIdx.x * STRIP;    // first input row-group
    const int plane = blockIdx.y;            // b*C + c

    const float* __restrict__ xp = x + (size_t)plane * PLANE_IN;

    const int grp = (tid >= 192) ? 1 : 0;
    const int t   = tid - 192 * grp;         // 0..191 = output float4 index
    const int m   = t % 3;
    const int q   = t / 3;

    // distinct global columns per m:
    //   m=0: {4q-1, 4q,   4q+1}   m=1: {4q+1, 4q+2, 4q+2}   m=2: {4q+3, 4q+2, 4q+4}
    int c0 = 4 * q - 1 + 2 * m;
    int c1 = 4 * q + (m ? 2 : 0);
    int c2 = 4 * q + 1 + m + (m >> 1);
    if (c0 < 0)      c0 = 1;                 // t=0:  col -1  -> x[1]
    if (c2 > W - 1)  c2 = W - 2;             // t=191: col 256 -> x[254]

    const bool  m0    = (m == 0);
    const bool  m2    = (m == 2);
    const bool  lastv = (t == 191);          // J=767 lives in .w of this thread

    float* __restrict__ opl = out + (size_t)plane * PLANE_OUT;

#pragma unroll
    for (int g = 0; g < STRIP / 2; ++g) {
        const int ig = base + 2 * g + grp;   // input row group 0..255
        // input rows for kx = 0,1,2 (reflected at boundaries)
        int r0 = ig - 1; if (ig == 0)     r0 = 1;
        int r2 = ig + 1; if (ig == H - 1) r2 = H - 2;
        const int rows[3] = { r0, ig, r2 };
        const bool lastrow = (ig == H - 1);

        float4* __restrict__ op =
            reinterpret_cast<float4*>(opl + (size_t)(3 * ig) * W3) + t;

#pragma unroll
        for (int kx = 0; kx < 3; ++kx) {
            const float* __restrict__ r = xp + rows[kx] * W;
            const float L0 = __ldg(r + c0);
            const float L1 = __ldg(r + c1);
            const float L2 = __ldg(r + c2);
            float4 v;
            v.x = L0;
            v.y = L1;
            v.z = m0 ? L2 : L0;
            v.w = m2 ? L2 : L1;
            if (kx == 2 && lastrow) {        // output row I=767: weight 2
                v.x *= 2.0f; v.y *= 2.0f; v.z *= 2.0f; v.w *= 2.0f;
            }
            if (lastv) v.w *= 2.0f;          // output col J=767: weight 2
            op[kx * (W3 / 4)] = v;
        }
    }
}

extern "C" void kernel_launch(void* const* d_in, const int* in_sizes, int n_in,
                              void* d_out, int out_size) {
    const float* x = (const float*)d_in[0];
    float* out = (float*)d_out;
    (void)in_sizes; (void)n_in; (void)out_size;

    dim3 grid(H / STRIP, B * C);   // 32 x 128 = 4096 blocks
    deform_direct_kernel<<<grid, NTHR>>>(x, out);
}

// round 11
// speedup vs baseline: 1.0398x; 1.0398x over previous
#include <cuda_runtime.h>

#define B 4
#define C 32
#define H 256
#define W 256
#define H3 768
#define W3 768
#define PLANE_IN  65536
#define PLANE_OUT 589824
#define SMROW 272              // skewed row: skew(260)=268 -> pad 272
#define STRIP 8                // input row-groups per block
#define SROWS (STRIP + 2)      // 10 staged input rows
#define NTHR 384

__device__ __forceinline__ int skew(int i) { return i + (i >> 5); }

// 32-byte evict_last load (the only vector width ptxas accepts with this hint).
__device__ __forceinline__ void ldg_el_8f(const float* p, float* v) {
    unsigned long long a, b, c, d;
    asm("ld.global.nc.L2::evict_last.v4.b64 {%0,%1,%2,%3}, [%4];"
        : "=l"(a), "=l"(b), "=l"(c), "=l"(d) : "l"(p));
    *reinterpret_cast<unsigned long long*>(v + 0) = a;
    *reinterpret_cast<unsigned long long*>(v + 2) = b;
    *reinterpret_cast<unsigned long long*>(v + 4) = c;
    *reinterpret_cast<unsigned long long*>(v + 6) = d;
}

// out[p, I, J] = x[p, reflect(I/3+I%3-1), reflect(J/3+J%3-1)]
//                * (I==767?2:1) * (J==767?2:1)
__global__ __launch_bounds__(NTHR)
void deform_strip_kernel(const float* __restrict__ x, float* __restrict__ out) {
    __shared__ float sm[SROWS][SMROW];

    const int tid   = threadIdx.x;
    const int base  = blockIdx.x * STRIP;   // first input row-group of strip
    const int plane = blockIdx.y;           // b*C + c

    const float* __restrict__ xp = x + (size_t)plane * PLANE_IN;

    // ---- stage SROWS reflected input rows: 10 rows * 32 8-float chunks ----
    if (tid < SROWS * 32) {
        const int s  = tid >> 5;            // smem row 0..9
        const int c8 = tid & 31;            // 8-float chunk 0..31
        int ri = base - 1 + s;
        ri = (ri < 0) ? 1 : ((ri > H - 1) ? H - 2 : ri);
        float v[8];
        ldg_el_8f(xp + ri * W + 8 * c8, v);
        float* r = sm[s];
        const int b0 = 8 * c8 + 4;
#pragma unroll
        for (int e = 0; e < 8; ++e)
            r[skew(b0 + e)] = v[e];
        if (c8 == 0)  r[3]   = v[1];        // col -1  -> x[1]   (skew(3)==3)
        if (c8 == 31) r[268] = v[6];        // col 256 -> x[254] (skew(260))
    }
    __syncthreads();

    // ---- compute: (grp, t); t = output float4 index within a row ----
    const int grp = (tid >= 192) ? 1 : 0;
    const int t   = tid - 192 * grp;        // 0..191
    const int m   = t % 3;
    const int q   = t / 3;

    // distinct column idx offsets per m:  m=0:{3,4,5} m=1:{5,6,6} m=2:{7,6,8}
    const int s0 = skew(4 * q + 3 + 2 * m);
    const int s1 = skew(4 * q + (m ? 6 : 4));
    const int s2 = skew(4 * q + 5 + m + (m >> 1));
    const bool m0    = (m == 0);
    const bool m2    = (m == 2);
    const bool lastv = (t == 191);          // J=767 lives in .w of this thread

    float* __restrict__ opl = out + (size_t)plane * PLANE_OUT;

#pragma unroll
    for (int g = 0; g < STRIP / 2; ++g) {
        const int gl = 2 * g + grp;         // local group 0..7
        const int ig = base + gl;           // global input row group
        float4* __restrict__ op =
            reinterpret_cast<float4*>(opl + (size_t)(3 * ig) * W3) + t;
        const bool lastrow = (ig == H - 1);

#pragma unroll
        for (int kx = 0; kx < 3; ++kx) {
            const float* r = sm[gl + kx];   // input rows ig-1..ig+1
            const float L0 = r[s0];
            const float L1 = r[s1];
            const float L2 = r[s2];
            float4 v;
            v.x = L0;
            v.y = L1;
            v.z = m0 ? L2 : L0;
            v.w = m2 ? L2 : L1;
            if (kx == 2 && lastrow) {       // output row I=767 weight 2
                v.x *= 2.0f; v.y *= 2.0f; v.z *= 2.0f; v.w *= 2.0f;
            }
            if (lastv) v.w *= 2.0f;         // output col J=767 weight 2
            op[kx * (W3 / 4)] = v;
        }
    }
}

extern "C" void kernel_launch(void* const* d_in, const int* in_sizes, int n_in,
                              void* d_out, int out_size) {
    const float* x = (const float*)d_in[0];
    float* out = (float*)d_out;
    (void)in_sizes; (void)n_in; (void)out_size;

    dim3 grid(H / STRIP, B * C);   // 32 x 128 = 4096 blocks
    deform_strip_kernel<<<grid, NTHR>>>(x, out);
}

// round 13
// speedup vs baseline: 1.1114x; 1.0689x over previous
#include <cuda_runtime.h>

#define B 4
#define C 32
#define H 256
#define W 256
#define H3 768
#define W3 768
#define PLANE_IN  65536
#define PLANE_OUT 589824
#define SMROW 272              // skewed row: skew(260)=268 -> pad 272
#define STRIP 8                // input row-groups per block
#define SROWS (STRIP + 2)      // 10 staged input rows
#define NTHR 288               // (96 chunks) x (3 kx)

__device__ __forceinline__ int skew(int i) { return i + (i >> 5); }

// 32-byte evict_last load
__device__ __forceinline__ void ldg_el_8f(const float* p, float* v) {
    unsigned long long a, b, c, d;
    asm("ld.global.nc.L2::evict_last.v4.b64 {%0,%1,%2,%3}, [%4];"
        : "=l"(a), "=l"(b), "=l"(c), "=l"(d) : "l"(p));
    *reinterpret_cast<unsigned long long*>(v + 0) = a;
    *reinterpret_cast<unsigned long long*>(v + 2) = b;
    *reinterpret_cast<unsigned long long*>(v + 4) = c;
    *reinterpret_cast<unsigned long long*>(v + 6) = d;
}

// 32-byte evict_first store
__device__ __forceinline__ void stg_ef_8f(float* p, const float* v) {
    const unsigned long long a = *reinterpret_cast<const unsigned long long*>(v + 0);
    const unsigned long long b = *reinterpret_cast<const unsigned long long*>(v + 2);
    const unsigned long long c = *reinterpret_cast<const unsigned long long*>(v + 4);
    const unsigned long long d = *reinterpret_cast<const unsigned long long*>(v + 6);
    asm volatile("st.global.L2::evict_first.v4.b64 [%0], {%1,%2,%3,%4};"
                 :: "l"(p), "l"(a), "l"(b), "l"(c), "l"(d) : "memory");
}

// out[p, I, J] = x[p, reflect(I/3+I%3-1), reflect(J/3+J%3-1)]
//                * (I==767?2:1) * (J==767?2:1)
__global__ __launch_bounds__(NTHR)
void deform_w32_kernel(const float* __restrict__ x, float* __restrict__ out) {
    __shared__ float sm[SROWS][SMROW];

    const int tid   = threadIdx.x;
    const int base  = blockIdx.x * STRIP;
    const int plane = blockIdx.y;

    const float* __restrict__ xp = x + (size_t)plane * PLANE_IN;

    // ---- stage SROWS reflected rows: 320 32B-chunks, 288 threads, 2 passes ----
#pragma unroll
    for (int k = 0; k < 2; ++k) {
        const int idx = tid + NTHR * k;
        if (idx < SROWS * 32) {
            const int s  = idx >> 5;        // smem row 0..9
            const int c8 = idx & 31;        // 8-float chunk
            int ri = base - 1 + s;
            ri = (ri < 0) ? 1 : ((ri > H - 1) ? H - 2 : ri);
            float v[8];
            ldg_el_8f(xp + ri * W + 8 * c8, v);
            float* r = sm[s];
            const int b0 = 8 * c8 + 4;
#pragma unroll
            for (int e = 0; e < 8; ++e)
                r[skew(b0 + e)] = v[e];
            if (c8 == 0)  r[3]   = v[1];    // col -1  -> x[1]
            if (c8 == 31) r[268] = v[6];    // col 256 -> x[254]
        }
    }
    __syncthreads();

    // ---- compute: thread = (c8, kx); 8 outputs per row, one 32B store ----
    const int c8 = tid % 96;                // output 8-float chunk in row
    const int kx = tid / 96;                // 0..2
    const int J0 = 8 * c8;

    // smem indices for the 8 output columns (reused across all groups)
    int sidx[8];
#pragma unroll
    for (int e = 0; e < 8; ++e) {
        const int J = J0 + e;
        int c = (J + 2 * (J % 3)) / 3 - 1;  // input col = J/3 + J%3 - 1
        if (c < 0)     c = 1;               // J=0:   col -1  -> x[1]
        if (c > W - 1) c = W - 2;           // J=767: col 256 -> x[254]
        sidx[e] = skew(c + 4);
    }
    const float wlast = (c8 == 95) ? 2.0f : 1.0f;   // J=767 weight (e==7)

    float* __restrict__ opl = out + (size_t)plane * PLANE_OUT;

#pragma unroll
    for (int g = 0; g < STRIP; ++g) {
        const int ig = base + g;
        const float* r = sm[g + kx];        // input row for out row 3*ig+kx
        float v[8];
#pragma unroll
        for (int e = 0; e < 8; ++e)
            v[e] = r[sidx[e]];
        if (kx == 2 && ig == H - 1) {       // output row I=767: weight 2
#pragma unroll
            for (int e = 0; e < 8; ++e)
                v[e] *= 2.0f;
        }
        v[7] *= wlast;                      // output col J=767: weight 2
        stg_ef_8f(opl + (size_t)(3 * ig + kx) * W3 + J0, v);
    }
}

extern "C" void kernel_launch(void* const* d_in, const int* in_sizes, int n_in,
                              void* d_out, int out_size) {
    const float* x = (const float*)d_in[0];
    float* out = (float*)d_out;
    (void)in_sizes; (void)n_in; (void)out_size;

    dim3 grid(H / STRIP, B * C);   // 32 x 128 = 4096 blocks
    deform_w32_kernel<<<grid, NTHR>>>(x, out);
}